// round 3
// baseline (speedup 1.0000x reference)
#include <cuda_runtime.h>
#include <math.h>

#define B_   32
#define C_   128
#define H_   56
#define W_   56
#define P_   (H_*W_)
#define E_   4
#define OUT_MAIN ((size_t)B_*C_*P_)

// ---------------- scratch (device globals; no allocs allowed) ----------------
__device__ float g_pooled[B_*C_];
__device__ int   g_assign[B_];
__device__ float g_weights[B_*E_];
__device__ float g_cd_eff[C_*C_*9];
__device__ float g_bayar_eff[C_*C_*25];
__device__ float g_y[(size_t)B_*3*C_*P_];   // srm dw out (B,384,P); reused as hf dw out (B,128,P)
__device__ float g_z[(size_t)B_*C_*P_];     // 1x1 conv out (B,128,P)
__device__ float g_mean[C_];
__device__ float g_inv[C_];

// ---------------- pooling: mean over H,W per (b,c) ----------------
__global__ void pool_kernel(const float* __restrict__ x) {
    int bc = blockIdx.x;
    float s = 0.f;
    for (int p = threadIdx.x; p < P_; p += 256)
        s += x[(size_t)bc*P_ + p];
    __shared__ float sh[256];
    sh[threadIdx.x] = s;
    __syncthreads();
    for (int st = 128; st > 0; st >>= 1) {
        if (threadIdx.x < st) sh[threadIdx.x] += sh[threadIdx.x + st];
        __syncthreads();
    }
    if (threadIdx.x == 0) g_pooled[bc] = sh[0] / (float)P_;
}

// ---------------- gating + tail outputs ----------------
__global__ void gate_kernel(const float* __restrict__ Wg, float* __restrict__ out_tail,
                            int write_tail) {
    int tid = threadIdx.x;
    if (tid < B_) {
        float l[E_] = {0.f,0.f,0.f,0.f};
        for (int c = 0; c < C_; c++) {
            float p = g_pooled[tid*C_ + c];
            #pragma unroll
            for (int e = 0; e < E_; e++) l[e] += p * Wg[c*E_ + e];
        }
        int best = 0; float bv = l[0];
        #pragma unroll
        for (int e = 1; e < E_; e++) if (l[e] > bv) { bv = l[e]; best = e; }
        g_assign[tid] = best;
        #pragma unroll
        for (int e = 0; e < E_; e++) g_weights[tid*E_ + e] = (e == best) ? 1.f : 0.f;
    }
    __syncthreads();
    if (tid == 0 && write_tail) {
        float cnt[E_] = {0.f,0.f,0.f,0.f};
        for (int b = 0; b < B_; b++) cnt[g_assign[b]] += 1.f;
        float mean = (float)B_ / (float)E_;
        float var = 0.f;
        for (int e = 0; e < E_; e++) { float d = cnt[e]-mean; var += d*d; }
        var /= (float)E_;
        out_tail[0] = var / (mean*mean + 1e-10f);   // aux_loss
        for (int e = 0; e < E_; e++) out_tail[1+e] = cnt[e];          // examples_per_expert
        for (int e = 0; e < E_; e++) out_tail[5+e] = cnt[e];          // expert_importance
        for (int i = 0; i < B_*E_; i++) out_tail[9+i] = g_weights[i]; // weights (B,E)
    }
}

// ---------------- weight prep ----------------
__global__ void prep_cd_kernel(const float* __restrict__ cd_w) {
    int oi = blockIdx.x*256 + threadIdx.x;
    if (oi >= C_*C_) return;
    float v[9]; float s = 0.f;
    #pragma unroll
    for (int k = 0; k < 9; k++) { v[k] = cd_w[oi*9 + k]; s += v[k]; }
    v[4] -= 0.7f * s;
    #pragma unroll
    for (int k = 0; k < 9; k++) g_cd_eff[oi*9 + k] = v[k];
}

__global__ void prep_bayar_kernel(const float* __restrict__ raw) {
    int oi = blockIdx.x*256 + threadIdx.x;
    if (oi >= C_*C_) return;
    float v[24]; float s = 0.f;
    #pragma unroll
    for (int k = 0; k < 24; k++) { v[k] = raw[oi*24 + k]; s += v[k]; }
    float invs = 1.f / s;
    #pragma unroll
    for (int k = 0; k < 12; k++) g_bayar_eff[oi*25 + k] = v[k]*invs;
    g_bayar_eff[oi*25 + 12] = -1.f;
    #pragma unroll
    for (int k = 12; k < 24; k++) g_bayar_eff[oi*25 + k + 1] = v[k]*invs;
}

// ---------------- direct conv (dense CxC), register-tiled ----------------
// Tile: 8x8 pixels, 32 out-channels, 128 threads; each thread 2x2 px * 4 co.
// WSRC: 0 = wext param, 1 = g_cd_eff, 2 = g_bayar_eff
template<int K, int PAD, bool ACCUM, int WSRC>
__global__ void conv_kernel(const float* __restrict__ x, const float* __restrict__ wext,
                            float* __restrict__ out, int sel) {
    const int b = blockIdx.z >> 2;
    if (sel >= 0 && g_assign[b] != sel) return;
    const int co0 = (blockIdx.z & 3) * 32;
    const int h0 = blockIdx.y * 8, w0 = blockIdx.x * 8;
    const float* wptr = (WSRC == 1) ? g_cd_eff : (WSRC == 2) ? g_bayar_eff : wext;
    constexpr int KK = K*K;
    constexpr int TS = 8 + 2*PAD;
    constexpr int CI = 8;
    __shared__ float xs[CI][TS][TS];
    __shared__ float ws[32][CI][KK];
    const int tid = threadIdx.x;              // 128 threads
    const int qid = tid & 15;
    const int qy = (qid >> 2) * 2, qx = (qid & 3) * 2;
    const int cg = tid >> 4;                  // 0..7 -> 4 consecutive co
    float acc[4][4];
    #pragma unroll
    for (int j = 0; j < 4; j++)
        #pragma unroll
        for (int q = 0; q < 4; q++) acc[j][q] = 0.f;

    for (int cc = 0; cc < C_; cc += CI) {
        for (int idx = tid; idx < CI*TS*TS; idx += 128) {
            int ci = idx / (TS*TS); int r = idx % (TS*TS);
            int ry = r / TS, rx = r % TS;
            int hh = h0 - PAD + ry, wi = w0 - PAD + rx;
            float v = 0.f;
            if (hh >= 0 && hh < H_ && wi >= 0 && wi < W_)
                v = x[((size_t)(b*C_ + cc + ci)*H_ + hh)*W_ + wi];
            xs[ci][ry][rx] = v;
        }
        for (int idx = tid; idx < 32*CI*KK; idx += 128) {
            int col = idx / (CI*KK); int rem = idx % (CI*KK);
            int ci = rem / KK; int k = rem % KK;
            ws[col][ci][k] = wptr[((size_t)(co0 + col)*C_ + cc + ci)*KK + k];
        }
        __syncthreads();
        for (int ci = 0; ci < CI; ci++) {
            float xv[K+1][K+1];
            #pragma unroll
            for (int r = 0; r < K+1; r++)
                #pragma unroll
                for (int s = 0; s < K+1; s++)
                    xv[r][s] = xs[ci][qy + r][qx + s];
            #pragma unroll
            for (int j = 0; j < 4; j++) {
                const float* wj = ws[cg*4 + j][ci];
                #pragma unroll
                for (int ky = 0; ky < K; ky++)
                    #pragma unroll
                    for (int kx = 0; kx < K; kx++) {
                        float wv = wj[ky*K + kx];
                        acc[j][0] += wv * xv[ky  ][kx  ];
                        acc[j][1] += wv * xv[ky  ][kx+1];
                        acc[j][2] += wv * xv[ky+1][kx  ];
                        acc[j][3] += wv * xv[ky+1][kx+1];
                    }
            }
        }
        __syncthreads();
    }
    #pragma unroll
    for (int j = 0; j < 4; j++) {
        int co = co0 + cg*4 + j;
        #pragma unroll
        for (int q = 0; q < 4; q++) {
            int hh = h0 + qy + (q >> 1), wi = w0 + qx + (q & 1);
            size_t o = ((size_t)(b*C_ + co)*H_ + hh)*W_ + wi;
            if (ACCUM) out[o] += acc[j][q];
            else       out[o] = acc[j][q];
        }
    }
}

// ---------------- srm depthwise 5x5 (3 fixed filters/channel) + hardtanh ----------------
__global__ void dw_srm_kernel(const float* __restrict__ x, const float* __restrict__ kern) {
    int b = blockIdx.x / C_, c = blockIdx.x % C_;
    __shared__ float xs[60][60];
    __shared__ float kf[3][25];
    int tid = threadIdx.x;  // 256
    for (int idx = tid; idx < 60*60; idx += 256) {
        int ry = idx / 60, rx = idx % 60;
        int hh = ry - 2, wi = rx - 2;
        float v = 0.f;
        if (hh >= 0 && hh < H_ && wi >= 0 && wi < W_)
            v = x[((size_t)(b*C_ + c)*H_ + hh)*W_ + wi];
        xs[ry][rx] = v;
    }
    if (tid < 75) kf[tid/25][tid%25] = kern[(c*3 + tid/25)*25 + tid%25];
    __syncthreads();
    for (int p = tid; p < P_; p += 256) {
        int hh = p / W_, wi = p % W_;
        float a0 = 0.f, a1 = 0.f, a2 = 0.f;
        #pragma unroll
        for (int ky = 0; ky < 5; ky++)
            #pragma unroll
            for (int kx = 0; kx < 5; kx++) {
                float v = xs[hh+ky][wi+kx];
                a0 += kf[0][ky*5+kx]*v;
                a1 += kf[1][ky*5+kx]*v;
                a2 += kf[2][ky*5+kx]*v;
            }
        a0 = fminf(fmaxf(a0, -3.f), 3.f);
        a1 = fminf(fmaxf(a1, -3.f), 3.f);
        a2 = fminf(fmaxf(a2, -3.f), 3.f);
        size_t base = ((size_t)b*3*C_ + c*3)*P_ + p;
        g_y[base        ] = a0;
        g_y[base +   P_ ] = a1;
        g_y[base + 2*P_ ] = a2;
    }
}

// ---------------- hf depthwise 3x3 (fixed Laplacian/channel) ----------------
__global__ void dw_hf_kernel(const float* __restrict__ x, const float* __restrict__ kern) {
    int b = blockIdx.x / C_, c = blockIdx.x % C_;
    __shared__ float xs[58][58];
    __shared__ float kf[9];
    int tid = threadIdx.x;  // 256
    for (int idx = tid; idx < 58*58; idx += 256) {
        int ry = idx / 58, rx = idx % 58;
        int hh = ry - 1, wi = rx - 1;
        float v = 0.f;
        if (hh >= 0 && hh < H_ && wi >= 0 && wi < W_)
            v = x[((size_t)(b*C_ + c)*H_ + hh)*W_ + wi];
        xs[ry][rx] = v;
    }
    if (tid < 9) kf[tid] = kern[c*9 + tid];
    __syncthreads();
    for (int p = tid; p < P_; p += 256) {
        int hh = p / W_, wi = p % W_;
        float a = 0.f;
        #pragma unroll
        for (int ky = 0; ky < 3; ky++)
            #pragma unroll
            for (int kx = 0; kx < 3; kx++)
                a += kf[ky*3+kx] * xs[hh+ky][wi+kx];
        g_y[((size_t)(b*C_ + c))*P_ + p] = a;
    }
}

// ---------------- 1x1 conv as GEMM: z[b,co,p] = sum_k W[co,k] * y[b,k,p] ----------------
template<int KD>
__global__ void gemm_kernel(const float* __restrict__ wmat) {
    int b = blockIdx.z;
    int co1 = blockIdx.y * 64;
    int p0  = blockIdx.x * 64;
    __shared__ float ys[16][64];
    __shared__ float ws2[64][17];
    int tid = threadIdx.x;           // 256
    int tp = tid & 15, tc = tid >> 4;
    float acc[4][4];
    #pragma unroll
    for (int j = 0; j < 4; j++)
        #pragma unroll
        for (int i = 0; i < 4; i++) acc[j][i] = 0.f;
    for (int kk = 0; kk < KD; kk += 16) {
        for (int idx = tid; idx < 1024; idx += 256) {
            int k = idx >> 6, p = idx & 63;
            ys[k][p] = g_y[(size_t)b*KD*P_ + (size_t)(kk + k)*P_ + p0 + p];
        }
        for (int idx = tid; idx < 1024; idx += 256) {
            int i = idx >> 4, k = idx & 15;
            ws2[i][k] = wmat[(co1 + i)*KD + kk + k];
        }
        __syncthreads();
        #pragma unroll
        for (int k = 0; k < 16; k++) {
            float wr[4], yr[4];
            #pragma unroll
            for (int jj = 0; jj < 4; jj++) wr[jj] = ws2[tc + 16*jj][k];
            #pragma unroll
            for (int ii = 0; ii < 4; ii++) yr[ii] = ys[k][tp + 16*ii];
            #pragma unroll
            for (int jj = 0; jj < 4; jj++)
                #pragma unroll
                for (int ii = 0; ii < 4; ii++)
                    acc[jj][ii] += wr[jj]*yr[ii];
        }
        __syncthreads();
    }
    #pragma unroll
    for (int jj = 0; jj < 4; jj++)
        #pragma unroll
        for (int ii = 0; ii < 4; ii++)
            g_z[((size_t)(b*C_ + co1 + tc + 16*jj))*P_ + p0 + tp + 16*ii] = acc[jj][ii];
}

// ---------------- BN statistics over (B,H,W) per channel ----------------
__global__ void bn_stats_kernel() {
    int c = blockIdx.x;
    double s = 0.0, s2 = 0.0;
    for (int t = threadIdx.x; t < B_*P_; t += 256) {
        int b = t / P_, p = t % P_;
        float v = g_z[((size_t)(b*C_ + c))*P_ + p];
        s += v; s2 += (double)v*v;
    }
    __shared__ double sh[256], sh2[256];
    sh[threadIdx.x] = s; sh2[threadIdx.x] = s2;
    __syncthreads();
    for (int st = 128; st > 0; st >>= 1) {
        if (threadIdx.x < st) { sh[threadIdx.x] += sh[threadIdx.x+st]; sh2[threadIdx.x] += sh2[threadIdx.x+st]; }
        __syncthreads();
    }
    if (threadIdx.x == 0) {
        double n = (double)B_*P_;
        double m = sh[0] / n;
        double var = sh2[0] / n - m*m;
        g_mean[c] = (float)m;
        g_inv[c]  = (float)(1.0 / sqrt(var + 1e-5));
    }
}

// ---------------- BN apply + ReLU + gated accumulate ----------------
__global__ void bn_apply_kernel(float* __restrict__ out, const float* __restrict__ gamma,
                                const float* __restrict__ beta, int sel) {
    int b = blockIdx.x / C_, c = blockIdx.x % C_;
    if (g_assign[b] != sel) return;
    float m = g_mean[c], inv = g_inv[c], ga = gamma[c], be = beta[c];
    for (int p = threadIdx.x; p < P_; p += 256) {
        size_t idx = ((size_t)(b*C_ + c))*P_ + p;
        float v = (g_z[idx] - m)*inv*ga + be;
        out[idx] += fmaxf(v, 0.f);
    }
}

// ---------------- launch ----------------
extern "C" void kernel_launch(void* const* d_in, const int* in_sizes, int n_in,
                              void* d_out, int out_size) {
    const float* x          = (const float*)d_in[0];
    const float* Wg         = (const float*)d_in[1];
    const float* cd_w       = (const float*)d_in[2];
    const float* bayar_w    = (const float*)d_in[3];
    const float* srm_kernel = (const float*)d_in[4];
    const float* srm_out_w  = (const float*)d_in[5];
    const float* srm_gamma  = (const float*)d_in[6];
    const float* srm_beta   = (const float*)d_in[7];
    const float* hf_kernel  = (const float*)d_in[8];
    const float* hf_out_w   = (const float*)d_in[9];
    const float* hf_gamma   = (const float*)d_in[10];
    const float* hf_beta    = (const float*)d_in[11];
    const float* shared_w   = (const float*)d_in[12];
    float* out = (float*)d_out;

    int write_tail = ((size_t)out_size >= OUT_MAIN + 137) ? 1 : 0;

    pool_kernel<<<B_*C_, 256>>>(x);
    gate_kernel<<<1, 128>>>(Wg, out + OUT_MAIN, write_tail);
    prep_cd_kernel<<<(C_*C_ + 255)/256, 256>>>(cd_w);
    prep_bayar_kernel<<<(C_*C_ + 255)/256, 256>>>(bayar_w);

    dim3 cgrid(7, 7, B_*4);
    // shared conv writes the whole output
    conv_kernel<3,1,false,0><<<cgrid, 128>>>(x, shared_w, out, -1);
    // cd expert (gated, folded into one 3x3)
    conv_kernel<3,1,true,1><<<cgrid, 128>>>(x, nullptr, out, 0);
    // bayar expert (gated, folded 5x5)
    conv_kernel<5,2,true,2><<<cgrid, 128>>>(x, nullptr, out, 1);

    // srm expert: full-batch (BN stats need all samples), gated add
    dw_srm_kernel<<<B_*C_, 256>>>(x, srm_kernel);
    gemm_kernel<3*C_><<<dim3(P_/64, C_/64, B_), 256>>>(srm_out_w);
    bn_stats_kernel<<<C_, 256>>>();
    bn_apply_kernel<<<B_*C_, 256>>>(out, srm_gamma, srm_beta, 2);

    // hf expert: full-batch, gated add
    dw_hf_kernel<<<B_*C_, 256>>>(x, hf_kernel);
    gemm_kernel<C_><<<dim3(P_/64, C_/64, B_), 256>>>(hf_out_w);
    bn_stats_kernel<<<C_, 256>>>();
    bn_apply_kernel<<<B_*C_, 256>>>(out, hf_gamma, hf_beta, 3);
}